// round 15
// baseline (speedup 1.0000x reference)
#include <cuda_runtime.h>
#include <cuda_fp16.h>
#include <math.h>
#include <stdint.h>

// Problem constants
#define Bsz 4096
#define Jn  17
#define Cn  512
#define Kn  3
#define TOKn 256
#define CHn 2048
#define M2  (Bsz*Jn)       // 69632
#define KC  (Kn*Cn)        // 1536
#define KCAT (KC + CHn)    // 3584
#define MR  (Bsz*Cn)       // 2097152 rows of (b,c)
#define EPSF 1e-5f

// ---------------- scratch (device globals; allocation-free rule) -------------
__device__ __half g_xah [M2 * KC];        // xa1, fp16                (214 MB)
__device__ float  g_x2  [Bsz*Jn*Cn];      // x + mlp1 + b12, fp32     (143 MB)
__device__ float  g_gc1 [Bsz*Jn*Cn];      // xa1@Wr1^T + b1m, fp32    (143 MB)
__device__ __half g_xn2h[Bsz*Jn*Cn];      // LN2 output, fp16         (71 MB)
__device__ __half g_cat [(size_t)M2 * KCAT]; // [xa2 | h], fp16       (499 MB)
__device__ __half g_xnh [(size_t)MR * 16];   // LN1 xn, k=16          (67 MB)
__device__ __half g_xn16[(size_t)MR];        // LN1 xn element 16     (4 MB)
__device__ __half g_Wr1h[Cn * KC];        // [o][k*512+c]
__device__ __half g_Wcat[Cn * KCAT];      // [o][Wr2 | W22]
__device__ __half g_W21h[CHn * Cn];       // [ch][c]
__device__ __half g_W11h[TOKn * 16];      // [t][j 0..15]
__device__ float  g_w11c16[TOKn];         // W11[t][16]
__device__ __half g_W12h[32 * TOKn];      // [j pad 32][t]
__device__ float  g_b1m [Jn * Cn];
__device__ float  g_b2m [Jn * Cn];        // includes b22

// fast gelu: tanh formulation with HW tanh.approx
__device__ __forceinline__ float gelu_fast(float v) {
    float inner = 0.7978845608028654f * fmaf(0.044715f * v, v * v, v);
    float t;
    asm("tanh.approx.f32 %0, %1;" : "=f"(t) : "f"(inner));
    return 0.5f * v * (1.0f + t);
}

// ---------------- PTX helpers ------------------------------------------------
__device__ __forceinline__ void mma_f16(float* d, const uint32_t* a, const uint32_t* b) {
    asm volatile(
        "mma.sync.aligned.m16n8k16.row.col.f32.f16.f16.f32 "
        "{%0,%1,%2,%3}, {%4,%5,%6,%7}, {%8,%9}, {%0,%1,%2,%3};"
        : "+f"(d[0]), "+f"(d[1]), "+f"(d[2]), "+f"(d[3])
        : "r"(a[0]), "r"(a[1]), "r"(a[2]), "r"(a[3]), "r"(b[0]), "r"(b[1]));
}
__device__ __forceinline__ void ldsm4(uint32_t* r, uint32_t addr) {
    asm volatile("ldmatrix.sync.aligned.m8n8.x4.shared.b16 {%0,%1,%2,%3}, [%4];"
                 : "=r"(r[0]), "=r"(r[1]), "=r"(r[2]), "=r"(r[3]) : "r"(addr));
}
__device__ __forceinline__ void cpasync16(uint32_t smem, const void* g) {
    asm volatile("cp.async.cg.shared.global [%0], [%1], 16;" :: "r"(smem), "l"(g));
}
__device__ __forceinline__ void cp_commit() {
    asm volatile("cp.async.commit_group;" ::: "memory");
}
template<int N_> __device__ __forceinline__ void cp_wait() {
    asm volatile("cp.async.wait_group %0;" :: "n"(N_) : "memory");
}
__device__ __forceinline__ uint32_t h2u(__half2 h) { return *(uint32_t*)&h; }

// ---------------- prep: weight layouts (fp16) + gcn bias ---------------------
__global__ void prep_kernel(const float* __restrict__ Wg1, const float* __restrict__ Wg2,
                            const float* __restrict__ W21, const float* __restrict__ W22,
                            const float* __restrict__ bg1, const float* __restrict__ bg2,
                            const float* __restrict__ adj,
                            const float* __restrict__ W11, const float* __restrict__ W12,
                            const float* __restrict__ b22)
{
    int i = blockIdx.x * 256 + threadIdx.x;
    const int S_Wr1 = Cn * KC;
    const int S_Wcat = Cn * KCAT;
    const int S_W21 = CHn * Cn;
    if (i < S_Wr1) {
        int o = i / KC, rem = i % KC;
        int k = rem >> 9, c = rem & 511;
        g_Wr1h[i] = __float2half_rn(Wg1[k * (Cn*Cn) + o * Cn + c]);
        return;
    }
    i -= S_Wr1;
    if (i < S_Wcat) {
        int o = i / KCAT, kk = i % KCAT;
        float v;
        if (kk < KC) {
            int k = kk >> 9, c = kk & 511;
            v = Wg2[k * (Cn*Cn) + o * Cn + c];
        } else {
            v = W22[o * CHn + (kk - KC)];
        }
        g_Wcat[i] = __float2half_rn(v);
        return;
    }
    i -= S_Wcat;
    if (i < S_W21) { g_W21h[i] = __float2half_rn(W21[i]); return; }
    i -= S_W21;
    if (i < TOKn * 16) {
        int t = i >> 4, j = i & 15;
        g_W11h[i] = __float2half_rn(W11[t * Jn + j]);
        return;
    }
    i -= TOKn * 16;
    if (i < TOKn) { g_w11c16[i] = W11[i * Jn + 16]; return; }
    i -= TOKn;
    if (i < 32 * TOKn) {
        int n = i >> 8, t = i & 255;
        g_W12h[i] = (n < Jn) ? __float2half_rn(W12[n * TOKn + t]) : __half(0.f);
        return;
    }
    i -= 32 * TOKn;
    if (i < Jn * Cn) {
        int w = i >> 9, o = i & 511;
        float s = 0.f;
        #pragma unroll
        for (int k = 0; k < Kn; k++) {
            float cs = 0.f;
            #pragma unroll
            for (int v = 0; v < Jn; v++) cs += adj[k*289 + v*17 + w];
            s += bg1[k * Cn + o] * cs;
        }
        g_b1m[i] = s;
        return;
    }
    i -= Jn * Cn;
    if (i < Jn * Cn) {
        int w = i >> 9, o = i & 511;
        float s = b22[o];
        #pragma unroll
        for (int k = 0; k < Kn; k++) {
            float cs = 0.f;
            #pragma unroll
            for (int v = 0; v < Jn; v++) cs += adj[k*289 + v*17 + w];
            s += bg2[k * Cn + o] * cs;
        }
        g_b2m[i] = s;
        return;
    }
}

// ---------------- stage 1: LN(J) -> xa1(fp16) + xnh(fp16, k16) + xn16 --------
__global__ __launch_bounds__(256) void stage1_kernel(
    const float* __restrict__ x, const float* __restrict__ adj,
    const float* __restrict__ g1, const float* __restrict__ be1)
{
    __shared__ float sadjT[Kn * Jn * 18];
    __shared__ float sg1[Jn], sbe1[Jn];

    const int tid = threadIdx.x;
    const int b = blockIdx.x;

    for (int i = tid; i < Kn*Jn*Jn; i += 256) { int k = i/289, r = i%289, v = r/17, w = r%17; sadjT[(k*17+w)*18 + v] = adj[i]; }
    for (int i = tid; i < Kn*Jn; i += 256) sadjT[i*18 + 17] = 0.f;
    if (tid < Jn) { sg1[tid] = g1[tid]; sbe1[tid] = be1[tid]; }
    __syncthreads();

    const int c0 = tid, c1 = tid + 256;
    const float* xb = x + (size_t)b * (Jn*Cn);

    float xr0[Jn], xr1[Jn];
    #pragma unroll
    for (int j = 0; j < Jn; j++) { xr0[j] = xb[j*Cn + c0]; xr1[j] = xb[j*Cn + c1]; }

    float mu0 = 0.f, mu1 = 0.f;
    #pragma unroll
    for (int j = 0; j < Jn; j++) { mu0 += xr0[j]; mu1 += xr1[j]; }
    mu0 *= (1.0f/17.0f); mu1 *= (1.0f/17.0f);
    float v0 = 0.f, v1 = 0.f;
    #pragma unroll
    for (int j = 0; j < Jn; j++) { float d0 = xr0[j]-mu0, d1 = xr1[j]-mu1; v0 += d0*d0; v1 += d1*d1; }
    float rs0 = rsqrtf(v0*(1.0f/17.0f) + EPSF);
    float rs1 = rsqrtf(v1*(1.0f/17.0f) + EPSF);

    float xn0[18], xn1[18];
    #pragma unroll
    for (int j = 0; j < Jn; j++) {
        xn0[j] = (xr0[j]-mu0)*rs0*sg1[j] + sbe1[j];
        xn1[j] = (xr1[j]-mu1)*rs1*sg1[j] + sbe1[j];
    }
    xn0[17] = 0.f; xn1[17] = 0.f;

    // xa1 (fp16)
    #pragma unroll
    for (int k = 0; k < Kn; k++) {
        #pragma unroll
        for (int w = 0; w < Jn; w++) {
            const float2* ar = (const float2*)&sadjT[(k*17+w)*18];
            float s0 = 0.f, s1 = 0.f;
            #pragma unroll
            for (int p = 0; p < 9; p++) {
                float2 a = ar[p];
                s0 += a.x*xn0[2*p] + a.y*xn0[2*p+1];
                s1 += a.x*xn1[2*p] + a.y*xn1[2*p+1];
            }
            int idx = (b*17 + w)*KC + k*Cn;
            g_xah[idx + c0] = __float2half_rn(s0);
            g_xah[idx + c1] = __float2half_rn(s1);
        }
    }

    // xnh rows (b*512+c): 16 halves (j=0..15); element 16 separate
    {
        __half2 hx[8];
        #pragma unroll
        for (int p = 0; p < 8; p++) hx[p] = __floats2half2_rn(xn0[2*p], xn0[2*p+1]);
        uint4* d0 = (uint4*)(g_xnh + ((size_t)b*512 + c0) * 16);
        const uint4* s = (const uint4*)hx;
        d0[0] = s[0]; d0[1] = s[1];
        g_xn16[(size_t)b*512 + c0] = __float2half_rn(xn0[16]);

        #pragma unroll
        for (int p = 0; p < 8; p++) hx[p] = __floats2half2_rn(xn1[2*p], xn1[2*p+1]);
        uint4* d1 = (uint4*)(g_xnh + ((size_t)b*512 + c1) * 16);
        d1[0] = s[0]; d1[1] = s[1];
        g_xn16[(size_t)b*512 + c1] = __float2half_rn(xn1[16]);
    }
}

// ---------------- fused MLP1 on tensor cores (k=16 + rank-1) -----------------
#define M1_XN   0            // [128][48B]   6144
#define M1_W11  6144         // [256][48B]   12288
#define M1_W12  18432        // [32][512B]   16384 (swizzled)
#define M1_X16  34816        // 128 floats
#define M1_WC16 35328        // 256 floats
#define M1_B11  36352        // 256 floats
#define M1_B12  37376        // 17 floats
#define M1_SMEM 37504

__global__ __launch_bounds__(256, 2) void mlp1_kernel(
    const float* __restrict__ x,
    const float* __restrict__ b11, const float* __restrict__ b12)
{
    extern __shared__ __align__(128) char sm[];
    uint32_t sbase;
    asm("{ .reg .u64 t; cvta.to.shared.u64 t, %1; cvt.u32.u64 %0, t; }" : "=r"(sbase) : "l"(sm));
    float* sx16  = (float*)(sm + M1_X16);
    float* swc16 = (float*)(sm + M1_WC16);
    float* sb11  = (float*)(sm + M1_B11);
    float* sb12  = (float*)(sm + M1_B12);

    const int tid = threadIdx.x, warp = tid >> 5, lane = tid & 31;
    const int rb = blockIdx.x * 128;

    {   // xnh tile: 128 rows x 32B, pitch 48
        const int r = tid >> 1, g = tid & 1;
        cpasync16(sbase + M1_XN + r*48 + g*16, g_xnh + ((size_t)(rb + r))*16 + g*8);
    }
    #pragma unroll
    for (int i = 0; i < 2; i++) {
        int ci = tid + 256*i;
        int row = ci >> 1, g = ci & 1;
        cpasync16(sbase + M1_W11 + row*48 + g*16, g_W11h + row*16 + g*8);
    }
    #pragma unroll
    for (int i = 0; i < 4; i++) {
        int ci = tid + 256*i;
        int row = ci >> 5, g = ci & 31;
        int gp = (g & ~7) | ((g ^ row) & 7);
        cpasync16(sbase + M1_W12 + row*512 + gp*16, g_W12h + row*256 + g*8);
    }
    cp_commit();
    if (tid < 128) sx16[tid] = __half2float(g_xn16[rb + tid]);
    swc16[tid] = g_w11c16[tid];
    sb11[tid] = b11[tid];
    if (tid < Jn) sb12[tid] = b12[tid];
    cp_wait<0>();
    __syncthreads();

    const int quad = lane >> 3, qr = lane & 7;
    const int kq = quad >> 1, qh = quad & 1;
    const int g = lane >> 2, tg = lane & 3;

    uint32_t af[4];
    ldsm4(af, sbase + M1_XN + (warp*16 + qh*8 + qr)*48 + (kq << 4));
    const float xnr0 = sx16[warp*16 + g];
    const float xnr1 = sx16[warp*16 + g + 8];

    float oacc[3][4];
    #pragma unroll
    for (int n = 0; n < 3; n++)
        #pragma unroll
        for (int e = 0; e < 4; e++) oacc[n][e] = 0.f;

    #pragma unroll
    for (int q = 0; q < 4; q++) {
        float hacc[8][4];
        #pragma unroll
        for (int n = 0; n < 8; n++)
            #pragma unroll
            for (int e = 0; e < 4; e++) hacc[n][e] = 0.f;

        #pragma unroll
        for (int nb = 0; nb < 4; nb++) {
            uint32_t bf[4];
            ldsm4(bf, sbase + M1_W11 + (q*64 + nb*16 + qh*8 + qr)*48 + (kq << 4));
            #pragma unroll
            for (int ni = 0; ni < 2; ni++) {
                uint32_t bb[2] = { bf[ni], bf[ni + 2] };
                mma_f16(hacc[nb*2 + ni], af, bb);
            }
        }

        uint32_t h2[8][2];
        #pragma unroll
        for (int nt = 0; nt < 8; nt++) {
            int t0 = q*64 + nt*8 + tg*2;
            float w0 = swc16[t0], w1 = swc16[t0 + 1];
            float b0 = sb11[t0],  b1 = sb11[t0 + 1];
            float h00 = hacc[nt][0] + xnr0*w0 + b0;
            float h01 = hacc[nt][1] + xnr0*w1 + b1;
            float h10 = hacc[nt][2] + xnr1*w0 + b0;
            float h11 = hacc[nt][3] + xnr1*w1 + b1;
            h2[nt][0] = h2u(__floats2half2_rn(gelu_fast(h00), gelu_fast(h01)));
            h2[nt][1] = h2u(__floats2half2_rn(gelu_fast(h10), gelu_fast(h11)));
        }

        #pragma unroll
        for (int ksl = 0; ksl < 4; ksl++) {
            uint32_t a2[4] = { h2[2*ksl][0], h2[2*ksl][1], h2[2*ksl+1][0], h2[2*ksl+1][1] };
            int kgrp = (q*4 + ksl)*2 + kq;
            #pragma unroll
            for (int nb2 = 0; nb2 < 2; nb2++) {
                const int brow = nb2*16 + qh*8 + qr;
                int gp = (kgrp & ~7) | ((kgrp ^ brow) & 7);
                uint32_t bf[4];
                ldsm4(bf, sbase + M1_W12 + brow*512 + (gp << 4));
                #pragma unroll
                for (int ni = 0; ni < 2; ni++) {
                    int nt2 = nb2*2 + ni;
                    if (nt2 < 3) {
                        uint32_t bb[2] = { bf[ni], bf[ni + 2] };
                        mma_f16(oacc[nt2], a2, bb);
                    }
                }
            }
        }
    }

    #pragma unroll
    for (int nt2 = 0; nt2 < 3; nt2++) {
        #pragma unroll
        for (int e = 0; e < 4; e++) {
            int j = nt2*8 + tg*2 + (e & 1);
            if (j < Jn) {
                int rowg = rb + warp*16 + g + ((e >> 1) * 8);
                int b = rowg >> 9, c = rowg & 511;
                size_t idx = ((size_t)b*17 + j)*512 + c;
                g_x2[idx] = x[idx] + oacc[nt2][e] + sb12[j];
            }
        }
    }
}

// ---------------- LN over C=512 on (g_x2 + g_gc1), fp16 out ------------------
__global__ __launch_bounds__(256) void ln2_kernel(const float* __restrict__ g2,
                                                  const float* __restrict__ be2)
{
    int row = blockIdx.x * 8 + (threadIdx.x >> 5);
    int lane = threadIdx.x & 31;
    const float4* xr = (const float4*)(g_x2 + (size_t)row * Cn);
    const float4* yr = (const float4*)(g_gc1 + (size_t)row * Cn);
    float4 a0 = xr[lane], a1 = xr[lane+32], a2 = xr[lane+64], a3 = xr[lane+96];
    float4 b0 = yr[lane], b1 = yr[lane+32], b2 = yr[lane+64], b3 = yr[lane+96];
    a0.x += b0.x; a0.y += b0.y; a0.z += b0.z; a0.w += b0.w;
    a1.x += b1.x; a1.y += b1.y; a1.z += b1.z; a1.w += b1.w;
    a2.x += b2.x; a2.y += b2.y; a2.z += b2.z; a2.w += b2.w;
    a3.x += b3.x; a3.y += b3.y; a3.z += b3.z; a3.w += b3.w;
    float s = a0.x+a0.y+a0.z+a0.w + a1.x+a1.y+a1.z+a1.w
            + a2.x+a2.y+a2.z+a2.w + a3.x+a3.y+a3.z+a3.w;
    #pragma unroll
    for (int off = 16; off; off >>= 1) s += __shfl_xor_sync(0xffffffffu, s, off);
    float mu = s * (1.0f/512.0f);
    float q = 0.f;
    {
        float d;
        d=a0.x-mu; q+=d*d; d=a0.y-mu; q+=d*d; d=a0.z-mu; q+=d*d; d=a0.w-mu; q+=d*d;
        d=a1.x-mu; q+=d*d; d=a1.y-mu; q+=d*d; d=a1.z-mu; q+=d*d; d=a1.w-mu; q+=d*d;
        d=a2.x-mu; q+=d*d; d=a2.y-mu; q+=d*d; d=a2.z-mu; q+=d*d; d=a2.w-mu; q+=d*d;
        d=a3.x-mu; q+=d*d; d=a3.y-mu; q+=d*d; d=a3.z-mu; q+=d*d; d=a3.w-mu; q+=d*d;
    }
    #pragma unroll
    for (int off = 16; off; off >>= 1) q += __shfl_xor_sync(0xffffffffu, q, off);
    float rstd = rsqrtf(q * (1.0f/512.0f) + EPSF);

    const float4* gg = (const float4*)g2;
    const float4* bb = (const float4*)be2;
    __half2* oh = (__half2*)(g_xn2h + (size_t)row * Cn);
    float* x2o = g_x2 + (size_t)row * Cn;   // persist summed residual for gemm2's aux
    #pragma unroll
    for (int i = 0; i < 4; i++) {
        float4 a = (i==0)?a0:(i==1)?a1:(i==2)?a2:a3;
        float4 g = gg[lane + i*32], e = bb[lane + i*32];
        int p = (lane + i*32) * 2;
        oh[p]   = __floats2half2_rn((a.x-mu)*rstd*g.x + e.x, (a.y-mu)*rstd*g.y + e.y);
        oh[p+1] = __floats2half2_rn((a.z-mu)*rstd*g.z + e.z, (a.w-mu)*rstd*g.w + e.w);
        *(float4*)&x2o[(lane + i*32)*4] = a;
    }
}

// ---------------- xa2 from xn2h -> g_cat[:, 0:1536] --------------------------
__global__ __launch_bounds__(256) void xa2_kernel(const float* __restrict__ adj)
{
    __shared__ float sadjT[Kn * Jn * 18];
    int tid = threadIdx.x;
    for (int i = tid; i < Kn*Jn*Jn; i += 256) { int k = i/289, r = i%289, v = r/17, w = r%17; sadjT[(k*17+w)*18 + v] = adj[i]; }
    for (int i = tid; i < Kn*Jn; i += 256) sadjT[i*18 + 17] = 0.f;
    __syncthreads();

    int gi = blockIdx.x * 256 + tid;
    int b = gi >> 9, c = gi & 511;
    float xv[18];
    #pragma unroll
    for (int v = 0; v < Jn; v++) xv[v] = __half2float(g_xn2h[(size_t)b*(Jn*Cn) + v*Cn + c]);
    xv[17] = 0.f;
    #pragma unroll
    for (int k = 0; k < Kn; k++) {
        #pragma unroll
        for (int w = 0; w < Jn; w++) {
            const float2* ar = (const float2*)&sadjT[(k*17+w)*18];
            float s = 0.f;
            #pragma unroll
            for (int p = 0; p < 9; p++) { float2 a = ar[p]; s += a.x*xv[2*p] + a.y*xv[2*p+1]; }
            g_cat[(size_t)(b*17 + w)*KCAT + k*Cn + c] = __float2half_rn(s);
        }
    }
}

// ---------------- fp16 tensor-core GEMM, 128x128x32, 6-stage cp.async --------
// EPI 1: g_cat[r][1536+c] = half(gelu(acc + biasv[c]))  (half out, stride 3584)
// EPI 2: out = aux + acc + b2m[(r%17)*512+c]            (float out, stride 512)
// EPI 3: out = acc + b1m[(r%17)*512+c]                  (pure store, stride 512)
#define NSTAGE 6
#define ABYTES 8192                      // 128 rows x 64 B
#define STAGE_BYTES (2*ABYTES)           // 16384
#define GEMM_SMEM (NSTAGE*STAGE_BYTES)   // 98304

template<int EPI>
__global__ __launch_bounds__(256, 2) void gemm_f16(
    const __half* __restrict__ A, const __half* __restrict__ Bw,
    void* __restrict__ outp, const float* __restrict__ biasv,
    const float* __restrict__ aux, int Kd)
{
    extern __shared__ __align__(128) char smem[];
    uint32_t sbase;
    asm("{ .reg .u64 t; cvta.to.shared.u64 t, %1; cvt.u32.u64 %0, t; }" : "=r"(sbase) : "l"(smem));

    const int tid  = threadIdx.x;
    const int warp = tid >> 5;
    const int lane = tid & 31;
    const int m0 = blockIdx.y * 128;
    const int n0 = blockIdx.x * 128;
    const int KT = Kd >> 5;

    const int lrow = tid >> 1;
    const int gsel = tid & 1;
    const int xw   = (lrow & 6) >> 1;
    const __half* gA = A  + (size_t)(m0 + lrow) * Kd + gsel * 16;
    const __half* gB = Bw + (size_t)(n0 + lrow) * Kd + gsel * 16;
    const uint32_t dA0 = sbase + lrow*64 + (((gsel*2 + 0) ^ xw) << 4);
    const uint32_t dA1 = sbase + lrow*64 + (((gsel*2 + 1) ^ xw) << 4);
    const uint32_t dB0 = dA0 + ABYTES;
    const uint32_t dB1 = dA1 + ABYTES;

    #pragma unroll
    for (int s = 0; s < NSTAGE - 1; s++) {
        const uint32_t so = s * STAGE_BYTES;
        if (s < KT) {
            cpasync16(dA0 + so, gA + s*32);
            cpasync16(dA1 + so, gA + s*32 + 8);
            cpasync16(dB0 + so, gB + s*32);
            cpasync16(dB1 + so, gB + s*32 + 8);
        }
        cp_commit();
    }

    const int wm = warp >> 2, wn = warp & 3;
    const int quad = lane >> 3, qr = lane & 7;
    const int kq = quad >> 1;
    const int arow0 = wm*64 + (quad & 1)*8 + qr;
    const int brow0 = wn*32 + (quad & 1)*8 + qr;
    const int xwa = (arow0 & 6) >> 1;
    const int xwb = (brow0 & 6) >> 1;
    const uint32_t aAddr = sbase + arow0*64;
    const uint32_t bAddr = sbase + ABYTES + brow0*64;

    float acc[4][4][4];
    #pragma unroll
    for (int mi = 0; mi < 4; mi++)
        #pragma unroll
        for (int ni = 0; ni < 4; ni++)
            #pragma unroll
            for (int e = 0; e < 4; e++) acc[mi][ni][e] = 0.f;

    int so_it = 0;
    for (int it = 0; it < KT; it++) {
        cp_wait<NSTAGE - 2>();
        __syncthreads();

        if (it + NSTAGE - 1 < KT) {
            int sn = so_it + NSTAGE - 1;
            if (sn >= NSTAGE) sn -= NSTAGE;
            const uint32_t so = sn * STAGE_BYTES;
            const __half* ga = gA + (it + NSTAGE - 1)*32;
            const __half* gb = gB + (it + NSTAGE - 1)*32;
            cpasync16(dA0 + so, ga);
            cpasync16(dA1 + so, ga + 8);
            cpasync16(dB0 + so, gb);
            cpasync16(dB1 + so, gb + 8);
        }
        cp_commit();

        const uint32_t so = so_it * STAGE_BYTES;
        so_it = (so_it + 1 == NSTAGE) ? 0 : so_it + 1;
        #pragma unroll
        for (int ks = 0; ks < 2; ks++) {
            uint32_t af[4][4], bf[2][4];
            #pragma unroll
            for (int mi = 0; mi < 4; mi++)
                ldsm4(af[mi], aAddr + so + mi*1024 + (((ks*2 + kq) ^ xwa) << 4));
            #pragma unroll
            for (int nb = 0; nb < 2; nb++)
                ldsm4(bf[nb], bAddr + so + nb*1024 + (((ks*2 + kq) ^ xwb) << 4));
            #pragma unroll
            for (int mi = 0; mi < 4; mi++)
                #pragma unroll
                for (int ni = 0; ni < 4; ni++) {
                    uint32_t bb[2] = { bf[ni >> 1][ni & 1], bf[ni >> 1][(ni & 1) + 2] };
                    mma_f16(acc[mi][ni], af[mi], bb);
                }
        }
    }

    const int g = lane >> 2, tg = lane & 3;
    #pragma unroll
    for (int mi = 0; mi < 4; mi++) {
        const int rbm = m0 + wm*64 + mi*16 + g;
        #pragma unroll
        for (int half = 0; half < 2; half++) {
            const int r = rbm + half*8;
            #pragma unroll
            for (int ni = 0; ni < 4; ni++) {
                const int c = n0 + wn*32 + ni*8 + tg*2;
                const float v0 = acc[mi][ni][half*2 + 0];
                const float v1 = acc[mi][ni][half*2 + 1];
                if (EPI == 1) {
                    __half2* p = (__half2*)((__half*)outp + (size_t)r * KCAT + KC + c);
                    const float* bb = biasv + c;
                    *p = __floats2half2_rn(gelu_fast(v0 + bb[0]), gelu_fast(v1 + bb[1]));
                } else if (EPI == 2) {
                    float* p = (float*)outp + (size_t)r * 512 + c;
                    const float* ax = aux + (size_t)r * 512 + c;
                    const float* bb = biasv + (r % 17) * 512 + c;
                    float2 a = *(const float2*)ax;
                    float2 o;
                    o.x = a.x + v0 + bb[0]; o.y = a.y + v1 + bb[1];
                    *(float2*)p = o;
                } else {   // EPI == 3: pure store acc + b1m
                    float* p = (float*)outp + (size_t)r * 512 + c;
                    const float* bb = biasv + (r % 17) * 512 + c;
                    float2 o;
                    o.x = v0 + bb[0]; o.y = v1 + bb[1];
                    *(float2*)p = o;
                }
            }
        }
    }
}

// ---------------- launch ------------------------------------------------------
extern "C" void kernel_launch(void* const* d_in, const int* in_sizes, int n_in,
                              void* d_out, int out_size)
{
    const float* x   = (const float*)d_in[0];
    const float* adj = (const float*)d_in[1];
    const float* g1  = (const float*)d_in[2];
    const float* be1 = (const float*)d_in[3];
    const float* g2  = (const float*)d_in[4];
    const float* be2 = (const float*)d_in[5];
    const float* Wg1 = (const float*)d_in[6];
    const float* bg1 = (const float*)d_in[7];
    const float* Wg2 = (const float*)d_in[8];
    const float* bg2 = (const float*)d_in[9];
    const float* W11 = (const float*)d_in[10];
    const float* b11 = (const float*)d_in[11];
    const float* W12 = (const float*)d_in[12];
    const float* b12 = (const float*)d_in[13];
    const float* W21 = (const float*)d_in[14];
    const float* b21 = (const float*)d_in[15];
    const float* W22 = (const float*)d_in[16];
    const float* b22 = (const float*)d_in[17];
    float* out = (float*)d_out;

    __half *p_xah, *p_xn2h, *p_cat, *p_Wr1h, *p_Wcat, *p_W21h;
    float *p_x2, *p_gc1, *p_b1m, *p_b2m;
    cudaGetSymbolAddress((void**)&p_xah,  g_xah);
    cudaGetSymbolAddress((void**)&p_x2,   g_x2);
    cudaGetSymbolAddress((void**)&p_gc1,  g_gc1);
    cudaGetSymbolAddress((void**)&p_xn2h, g_xn2h);
    cudaGetSymbolAddress((void**)&p_cat,  g_cat);
    cudaGetSymbolAddress((void**)&p_Wr1h, g_Wr1h);
    cudaGetSymbolAddress((void**)&p_Wcat, g_Wcat);
    cudaGetSymbolAddress((void**)&p_W21h, g_W21h);
    cudaGetSymbolAddress((void**)&p_b1m,  g_b1m);
    cudaGetSymbolAddress((void**)&p_b2m,  g_b2m);

    static cudaStream_t s2 = nullptr;
    static cudaEvent_t evFork = nullptr, evJoin = nullptr, evFork2 = nullptr, evJoin2 = nullptr,
                       evFork3 = nullptr, evJoin3 = nullptr;
    if (s2 == nullptr) {
        cudaStreamCreateWithFlags(&s2, cudaStreamNonBlocking);
        cudaEventCreateWithFlags(&evFork,  cudaEventDisableTiming);
        cudaEventCreateWithFlags(&evJoin,  cudaEventDisableTiming);
        cudaEventCreateWithFlags(&evFork2, cudaEventDisableTiming);
        cudaEventCreateWithFlags(&evJoin2, cudaEventDisableTiming);
        cudaEventCreateWithFlags(&evFork3, cudaEventDisableTiming);
        cudaEventCreateWithFlags(&evJoin3, cudaEventDisableTiming);
        cudaFuncSetAttribute(gemm_f16<1>, cudaFuncAttributeMaxDynamicSharedMemorySize, GEMM_SMEM);
        cudaFuncSetAttribute(gemm_f16<2>, cudaFuncAttributeMaxDynamicSharedMemorySize, GEMM_SMEM);
        cudaFuncSetAttribute(gemm_f16<3>, cudaFuncAttributeMaxDynamicSharedMemorySize, GEMM_SMEM);
        cudaFuncSetAttribute(mlp1_kernel, cudaFuncAttributeMaxDynamicSharedMemorySize, M1_SMEM);
    }

    // fork 1: prep (weights) on s2, concurrent with stage1 on main
    cudaEventRecord(evFork, 0);
    cudaStreamWaitEvent(s2, evFork, 0);
    {
        int total = Cn*KC + Cn*KCAT + CHn*Cn + TOKn*16 + TOKn + 32*TOKn + 2*(Jn*Cn);
        prep_kernel<<<(total + 255)/256, 256, 0, s2>>>(Wg1, Wg2, W21, W22, bg1, bg2, adj, W11, W12, b22);
    }
    cudaEventRecord(evJoin, s2);

    stage1_kernel<<<Bsz, 256>>>(x, adj, g1, be1);
    cudaStreamWaitEvent(0, evJoin, 0);

    // fork 3: mlp1 (MUFU/FMA-heavy, writes g_x2) on s2,
    //         concurrent with gemm0 (tensor-bound, writes g_gc1) on main
    cudaEventRecord(evFork3, 0);
    cudaStreamWaitEvent(s2, evFork3, 0);
    mlp1_kernel<<<MR/128, 256, M1_SMEM, s2>>>(x, b11, b12);
    cudaEventRecord(evJoin3, s2);

    // GCN1: g_gc1 = xa1 @ Wr1^T + b1m   (pure store, no g_x2 dependency)
    gemm_f16<3><<<dim3(Cn/128, M2/128), 256, GEMM_SMEM>>>(p_xah, p_Wr1h, p_gc1, p_b1m, nullptr, KC);

    // join: ln2 needs both g_x2 (mlp1) and g_gc1 (gemm0)
    cudaStreamWaitEvent(0, evJoin3, 0);

    // LN2 over (g_x2 + g_gc1); persists sum back into g_x2 for gemm2's aux
    ln2_kernel<<<M2/8, 256>>>(g2, be2);

    // fork 2: xa2 (memory-bound) on s2 ∥ gemm1 (tensor-bound) on main
    cudaEventRecord(evFork2, 0);
    cudaStreamWaitEvent(s2, evFork2, 0);
    xa2_kernel<<<(Bsz*Cn)/256, 256, 0, s2>>>(adj);
    cudaEventRecord(evJoin2, s2);

    gemm_f16<1><<<dim3(CHn/128, M2/128), 256, GEMM_SMEM>>>(p_xn2h, p_W21h, p_cat, b21, nullptr, Cn);

    cudaStreamWaitEvent(0, evJoin2, 0);

    // final fused GCN2+MLP2dn: out = x2 + cat @ Wcat^T + b2m'   (K=3584, N=512)
    gemm_f16<2><<<dim3(Cn/128, M2/128), 256, GEMM_SMEM>>>(p_cat, p_Wcat, out, p_b2m, p_x2, KCAT);
}

// round 16
// speedup vs baseline: 1.0282x; 1.0282x over previous
#include <cuda_runtime.h>
#include <cuda_fp16.h>
#include <math.h>
#include <stdint.h>

// Problem constants
#define Bsz 4096
#define Jn  17
#define Cn  512
#define Kn  3
#define TOKn 256
#define CHn 2048
#define M2  (Bsz*Jn)       // 69632
#define KC  (Kn*Cn)        // 1536
#define KCAT (KC + CHn)    // 3584
#define MR  (Bsz*Cn)       // 2097152 rows of (b,c)
#define EPSF 1e-5f

// ---------------- scratch (device globals; allocation-free rule) -------------
__device__ __half g_xah [M2 * KC];        // xa1, fp16                (214 MB)
__device__ float  g_x2  [Bsz*Jn*Cn];      // stage-1 result, fp32     (143 MB)
__device__ __half g_xn2h[Bsz*Jn*Cn];      // LN2 output, fp16         (71 MB)
__device__ __half g_cat [(size_t)M2 * KCAT]; // [xa2 | h], fp16       (499 MB)
__device__ __half g_xnh [(size_t)MR * 16];   // LN1 xn, k=16          (67 MB)
__device__ __half g_xn16[(size_t)MR];        // LN1 xn element 16     (4 MB)
__device__ __half g_Wr1h[Cn * KC];        // [o][k*512+c]
__device__ __half g_Wcat[Cn * KCAT];      // [o][Wr2 | W22]
__device__ __half g_W21h[CHn * Cn];       // [ch][c]
__device__ __half g_W11h[TOKn * 16];      // [t][j 0..15]
__device__ float  g_w11c16[TOKn];         // W11[t][16]
__device__ __half g_W12h[32 * TOKn];      // [j pad 32][t]
__device__ float  g_b1m [Jn * Cn];
__device__ float  g_b2m [Jn * Cn];        // includes b22

__device__ __forceinline__ uint32_t h2u(__half2 h) { return *(uint32_t*)&h; }

// packed half2 gelu: tanh formulation with HW tanh.approx.f16x2 (1 MUFU / 2 vals).
// inner = v*(c0 + c1*v^2); saturation: v large -> inner inf -> tanh 1 -> gelu v (correct).
__device__ __forceinline__ __half2 gelu_h2(__half2 v) {
    const __half2 c0 = __floats2half2_rn(0.7978845608f, 0.7978845608f);
    const __half2 c1 = __floats2half2_rn(0.0356774081f, 0.0356774081f);
    const __half2 hhalf = __floats2half2_rn(0.5f, 0.5f);
    const __half2 hone  = __floats2half2_rn(1.0f, 1.0f);
    __half2 v2 = __hmul2(v, v);
    __half2 inner = __hmul2(v, __hfma2(c1, v2, c0));
    uint32_t t;
    asm("tanh.approx.f16x2 %0, %1;" : "=r"(t) : "r"(h2u(inner)));
    __half2 th = *(__half2*)&t;
    return __hmul2(__hmul2(hhalf, v), __hadd2(hone, th));
}

// ---------------- PTX helpers ------------------------------------------------
__device__ __forceinline__ void mma_f16(float* d, const uint32_t* a, const uint32_t* b) {
    asm volatile(
        "mma.sync.aligned.m16n8k16.row.col.f32.f16.f16.f32 "
        "{%0,%1,%2,%3}, {%4,%5,%6,%7}, {%8,%9}, {%0,%1,%2,%3};"
        : "+f"(d[0]), "+f"(d[1]), "+f"(d[2]), "+f"(d[3])
        : "r"(a[0]), "r"(a[1]), "r"(a[2]), "r"(a[3]), "r"(b[0]), "r"(b[1]));
}
__device__ __forceinline__ void ldsm4(uint32_t* r, uint32_t addr) {
    asm volatile("ldmatrix.sync.aligned.m8n8.x4.shared.b16 {%0,%1,%2,%3}, [%4];"
                 : "=r"(r[0]), "=r"(r[1]), "=r"(r[2]), "=r"(r[3]) : "r"(addr));
}
__device__ __forceinline__ void cpasync16(uint32_t smem, const void* g) {
    asm volatile("cp.async.cg.shared.global [%0], [%1], 16;" :: "r"(smem), "l"(g));
}
__device__ __forceinline__ void cp_commit() {
    asm volatile("cp.async.commit_group;" ::: "memory");
}
template<int N_> __device__ __forceinline__ void cp_wait() {
    asm volatile("cp.async.wait_group %0;" :: "n"(N_) : "memory");
}

// ---------------- prep: weight layouts (fp16) + gcn bias ---------------------
__global__ void prep_kernel(const float* __restrict__ Wg1, const float* __restrict__ Wg2,
                            const float* __restrict__ W21, const float* __restrict__ W22,
                            const float* __restrict__ bg1, const float* __restrict__ bg2,
                            const float* __restrict__ adj,
                            const float* __restrict__ W11, const float* __restrict__ W12,
                            const float* __restrict__ b22)
{
    int i = blockIdx.x * 256 + threadIdx.x;
    const int S_Wr1 = Cn * KC;
    const int S_Wcat = Cn * KCAT;
    const int S_W21 = CHn * Cn;
    if (i < S_Wr1) {
        int o = i / KC, rem = i % KC;
        int k = rem >> 9, c = rem & 511;
        g_Wr1h[i] = __float2half_rn(Wg1[k * (Cn*Cn) + o * Cn + c]);
        return;
    }
    i -= S_Wr1;
    if (i < S_Wcat) {
        int o = i / KCAT, kk = i % KCAT;
        float v;
        if (kk < KC) {
            int k = kk >> 9, c = kk & 511;
            v = Wg2[k * (Cn*Cn) + o * Cn + c];
        } else {
            v = W22[o * CHn + (kk - KC)];
        }
        g_Wcat[i] = __float2half_rn(v);
        return;
    }
    i -= S_Wcat;
    if (i < S_W21) { g_W21h[i] = __float2half_rn(W21[i]); return; }
    i -= S_W21;
    if (i < TOKn * 16) {
        int t = i >> 4, j = i & 15;
        g_W11h[i] = __float2half_rn(W11[t * Jn + j]);
        return;
    }
    i -= TOKn * 16;
    if (i < TOKn) { g_w11c16[i] = W11[i * Jn + 16]; return; }
    i -= TOKn;
    if (i < 32 * TOKn) {
        int n = i >> 8, t = i & 255;
        g_W12h[i] = (n < Jn) ? __float2half_rn(W12[n * TOKn + t]) : __half(0.f);
        return;
    }
    i -= 32 * TOKn;
    if (i < Jn * Cn) {
        int w = i >> 9, o = i & 511;
        float s = 0.f;
        #pragma unroll
        for (int k = 0; k < Kn; k++) {
            float cs = 0.f;
            #pragma unroll
            for (int v = 0; v < Jn; v++) cs += adj[k*289 + v*17 + w];
            s += bg1[k * Cn + o] * cs;
        }
        g_b1m[i] = s;
        return;
    }
    i -= Jn * Cn;
    if (i < Jn * Cn) {
        int w = i >> 9, o = i & 511;
        float s = b22[o];
        #pragma unroll
        for (int k = 0; k < Kn; k++) {
            float cs = 0.f;
            #pragma unroll
            for (int v = 0; v < Jn; v++) cs += adj[k*289 + v*17 + w];
            s += bg2[k * Cn + o] * cs;
        }
        g_b2m[i] = s;
        return;
    }
}

// ---------------- stage 1: LN(J) -> xa1(fp16) + xnh(fp16, k16) + xn16 --------
__global__ __launch_bounds__(256) void stage1_kernel(
    const float* __restrict__ x, const float* __restrict__ adj,
    const float* __restrict__ g1, const float* __restrict__ be1)
{
    __shared__ float sadjT[Kn * Jn * 18];
    __shared__ float sg1[Jn], sbe1[Jn];

    const int tid = threadIdx.x;
    const int b = blockIdx.x;

    for (int i = tid; i < Kn*Jn*Jn; i += 256) { int k = i/289, r = i%289, v = r/17, w = r%17; sadjT[(k*17+w)*18 + v] = adj[i]; }
    for (int i = tid; i < Kn*Jn; i += 256) sadjT[i*18 + 17] = 0.f;
    if (tid < Jn) { sg1[tid] = g1[tid]; sbe1[tid] = be1[tid]; }
    __syncthreads();

    const int c0 = tid, c1 = tid + 256;
    const float* xb = x + (size_t)b * (Jn*Cn);

    float xr0[Jn], xr1[Jn];
    #pragma unroll
    for (int j = 0; j < Jn; j++) { xr0[j] = xb[j*Cn + c0]; xr1[j] = xb[j*Cn + c1]; }

    float mu0 = 0.f, mu1 = 0.f;
    #pragma unroll
    for (int j = 0; j < Jn; j++) { mu0 += xr0[j]; mu1 += xr1[j]; }
    mu0 *= (1.0f/17.0f); mu1 *= (1.0f/17.0f);
    float v0 = 0.f, v1 = 0.f;
    #pragma unroll
    for (int j = 0; j < Jn; j++) { float d0 = xr0[j]-mu0, d1 = xr1[j]-mu1; v0 += d0*d0; v1 += d1*d1; }
    float rs0 = rsqrtf(v0*(1.0f/17.0f) + EPSF);
    float rs1 = rsqrtf(v1*(1.0f/17.0f) + EPSF);

    float xn0[18], xn1[18];
    #pragma unroll
    for (int j = 0; j < Jn; j++) {
        xn0[j] = (xr0[j]-mu0)*rs0*sg1[j] + sbe1[j];
        xn1[j] = (xr1[j]-mu1)*rs1*sg1[j] + sbe1[j];
    }
    xn0[17] = 0.f; xn1[17] = 0.f;

    // xa1 (fp16)
    #pragma unroll
    for (int k = 0; k < Kn; k++) {
        #pragma unroll
        for (int w = 0; w < Jn; w++) {
            const float2* ar = (const float2*)&sadjT[(k*17+w)*18];
            float s0 = 0.f, s1 = 0.f;
            #pragma unroll
            for (int p = 0; p < 9; p++) {
                float2 a = ar[p];
                s0 += a.x*xn0[2*p] + a.y*xn0[2*p+1];
                s1 += a.x*xn1[2*p] + a.y*xn1[2*p+1];
            }
            int idx = (b*17 + w)*KC + k*Cn;
            g_xah[idx + c0] = __float2half_rn(s0);
            g_xah[idx + c1] = __float2half_rn(s1);
        }
    }

    // xnh rows (b*512+c): 16 halves (j=0..15); element 16 separate
    {
        __half2 hx[8];
        #pragma unroll
        for (int p = 0; p < 8; p++) hx[p] = __floats2half2_rn(xn0[2*p], xn0[2*p+1]);
        uint4* d0 = (uint4*)(g_xnh + ((size_t)b*512 + c0) * 16);
        const uint4* s = (const uint4*)hx;
        d0[0] = s[0]; d0[1] = s[1];
        g_xn16[(size_t)b*512 + c0] = __float2half_rn(xn0[16]);

        #pragma unroll
        for (int p = 0; p < 8; p++) hx[p] = __floats2half2_rn(xn1[2*p], xn1[2*p+1]);
        uint4* d1 = (uint4*)(g_xnh + ((size_t)b*512 + c1) * 16);
        d1[0] = s[0]; d1[1] = s[1];
        g_xn16[(size_t)b*512 + c1] = __float2half_rn(xn1[16]);
    }
}

// ---------------- fused MLP1 on tensor cores (k=16 + rank-1) -----------------
#define M1_XN   0            // [128][48B]   6144
#define M1_W11  6144         // [256][48B]   12288
#define M1_W12  18432        // [32][512B]   16384 (swizzled)
#define M1_X16  34816        // 128 floats
#define M1_WC16 35328        // 256 floats
#define M1_B11  36352        // 256 floats
#define M1_B12  37376        // 17 floats
#define M1_SMEM 37504

__global__ __launch_bounds__(256, 2) void mlp1_kernel(
    const float* __restrict__ x,
    const float* __restrict__ b11, const float* __restrict__ b12)
{
    extern __shared__ __align__(128) char sm[];
    uint32_t sbase;
    asm("{ .reg .u64 t; cvta.to.shared.u64 t, %1; cvt.u32.u64 %0, t; }" : "=r"(sbase) : "l"(sm));
    float* sx16  = (float*)(sm + M1_X16);
    float* swc16 = (float*)(sm + M1_WC16);
    float* sb11  = (float*)(sm + M1_B11);
    float* sb12  = (float*)(sm + M1_B12);

    const int tid = threadIdx.x, warp = tid >> 5, lane = tid & 31;
    const int rb = blockIdx.x * 128;

    {   // xnh tile: 128 rows x 32B, pitch 48
        const int r = tid >> 1, g = tid & 1;
        cpasync16(sbase + M1_XN + r*48 + g*16, g_xnh + ((size_t)(rb + r))*16 + g*8);
    }
    #pragma unroll
    for (int i = 0; i < 2; i++) {
        int ci = tid + 256*i;
        int row = ci >> 1, g = ci & 1;
        cpasync16(sbase + M1_W11 + row*48 + g*16, g_W11h + row*16 + g*8);
    }
    #pragma unroll
    for (int i = 0; i < 4; i++) {
        int ci = tid + 256*i;
        int row = ci >> 5, g = ci & 31;
        int gp = (g & ~7) | ((g ^ row) & 7);
        cpasync16(sbase + M1_W12 + row*512 + gp*16, g_W12h + row*256 + g*8);
    }
    cp_commit();
    if (tid < 128) sx16[tid] = __half2float(g_xn16[rb + tid]);
    swc16[tid] = g_w11c16[tid];
    sb11[tid] = b11[tid];
    if (tid < Jn) sb12[tid] = b12[tid];
    cp_wait<0>();
    __syncthreads();

    const int quad = lane >> 3, qr = lane & 7;
    const int kq = quad >> 1, qh = quad & 1;
    const int g = lane >> 2, tg = lane & 3;

    uint32_t af[4];
    ldsm4(af, sbase + M1_XN + (warp*16 + qh*8 + qr)*48 + (kq << 4));
    const float xnr0 = sx16[warp*16 + g];
    const float xnr1 = sx16[warp*16 + g + 8];

    float oacc[3][4];
    #pragma unroll
    for (int n = 0; n < 3; n++)
        #pragma unroll
        for (int e = 0; e < 4; e++) oacc[n][e] = 0.f;

    #pragma unroll
    for (int q = 0; q < 4; q++) {
        float hacc[8][4];
        #pragma unroll
        for (int n = 0; n < 8; n++)
            #pragma unroll
            for (int e = 0; e < 4; e++) hacc[n][e] = 0.f;

        #pragma unroll
        for (int nb = 0; nb < 4; nb++) {
            uint32_t bf[4];
            ldsm4(bf, sbase + M1_W11 + (q*64 + nb*16 + qh*8 + qr)*48 + (kq << 4));
            #pragma unroll
            for (int ni = 0; ni < 2; ni++) {
                uint32_t bb[2] = { bf[ni], bf[ni + 2] };
                mma_f16(hacc[nb*2 + ni], af, bb);
            }
        }

        // rank-1 + bias (fp32) -> pack -> packed half2 gelu (1 MUFU / 2 vals)
        uint32_t h2[8][2];
        #pragma unroll
        for (int nt = 0; nt < 8; nt++) {
            int t0 = q*64 + nt*8 + tg*2;
            float w0 = swc16[t0], w1 = swc16[t0 + 1];
            float b0 = sb11[t0],  b1 = sb11[t0 + 1];
            __half2 p0 = __floats2half2_rn(hacc[nt][0] + xnr0*w0 + b0,
                                           hacc[nt][1] + xnr0*w1 + b1);
            __half2 p1 = __floats2half2_rn(hacc[nt][2] + xnr1*w0 + b0,
                                           hacc[nt][3] + xnr1*w1 + b1);
            h2[nt][0] = h2u(gelu_h2(p0));
            h2[nt][1] = h2u(gelu_h2(p1));
        }

        #pragma unroll
        for (int ksl = 0; ksl < 4; ksl++) {
            uint32_t a2[4] = { h2[2*ksl][0], h2[2*ksl][1], h2[2*ksl+1][0], h2[2*ksl+1][1] };
            int kgrp = (q*4 + ksl)*2 + kq;
            #pragma unroll
            for (int nb2 = 0; nb2 < 2; nb2++) {
                const int brow = nb2*16 + qh*8 + qr;
                int gp = (kgrp & ~7) | ((kgrp ^ brow) & 7);
                uint32_t bf[4];
                ldsm4(bf, sbase + M1_W12 + brow*512 + (gp << 4));
                #pragma unroll
                for (int ni = 0; ni < 2; ni++) {
                    int nt2 = nb2*2 + ni;
                    if (nt2 < 3) {
                        uint32_t bb[2] = { bf[ni], bf[ni + 2] };
                        mma_f16(oacc[nt2], a2, bb);
                    }
                }
            }
        }
    }

    #pragma unroll
    for (int nt2 = 0; nt2 < 3; nt2++) {
        #pragma unroll
        for (int e = 0; e < 4; e++) {
            int j = nt2*8 + tg*2 + (e & 1);
            if (j < Jn) {
                int rowg = rb + warp*16 + g + ((e >> 1) * 8);
                int b = rowg >> 9, c = rowg & 511;
                size_t idx = ((size_t)b*17 + j)*512 + c;
                g_x2[idx] = x[idx] + oacc[nt2][e] + sb12[j];
            }
        }
    }
}

// ---------------- LN over C=512 (one warp per row), fp16 out -----------------
__global__ __launch_bounds__(256) void ln2_kernel(const float* __restrict__ g2,
                                                  const float* __restrict__ be2)
{
    int row = blockIdx.x * 8 + (threadIdx.x >> 5);
    int lane = threadIdx.x & 31;
    const float4* xr = (const float4*)(g_x2 + (size_t)row * Cn);
    float4 a0 = xr[lane], a1 = xr[lane+32], a2 = xr[lane+64], a3 = xr[lane+96];
    float s = a0.x+a0.y+a0.z+a0.w + a1.x+a1.y+a1.z+a1.w
            + a2.x+a2.y+a2.z+a2.w + a3.x+a3.y+a3.z+a3.w;
    #pragma unroll
    for (int off = 16; off; off >>= 1) s += __shfl_xor_sync(0xffffffffu, s, off);
    float mu = s * (1.0f/512.0f);
    float q = 0.f;
    {
        float d;
        d=a0.x-mu; q+=d*d; d=a0.y-mu; q+=d*d; d=a0.z-mu; q+=d*d; d=a0.w-mu; q+=d*d;
        d=a1.x-mu; q+=d*d; d=a1.y-mu; q+=d*d; d=a1.z-mu; q+=d*d; d=a1.w-mu; q+=d*d;
        d=a2.x-mu; q+=d*d; d=a2.y-mu; q+=d*d; d=a2.z-mu; q+=d*d; d=a2.w-mu; q+=d*d;
        d=a3.x-mu; q+=d*d; d=a3.y-mu; q+=d*d; d=a3.z-mu; q+=d*d; d=a3.w-mu; q+=d*d;
    }
    #pragma unroll
    for (int off = 16; off; off >>= 1) q += __shfl_xor_sync(0xffffffffu, q, off);
    float rstd = rsqrtf(q * (1.0f/512.0f) + EPSF);

    const float4* gg = (const float4*)g2;
    const float4* bb = (const float4*)be2;
    __half2* oh = (__half2*)(g_xn2h + (size_t)row * Cn);
    #pragma unroll
    for (int i = 0; i < 4; i++) {
        float4 a = (i==0)?a0:(i==1)?a1:(i==2)?a2:a3;
        float4 g = gg[lane + i*32], e = bb[lane + i*32];
        int p = (lane + i*32) * 2;
        oh[p]   = __floats2half2_rn((a.x-mu)*rstd*g.x + e.x, (a.y-mu)*rstd*g.y + e.y);
        oh[p+1] = __floats2half2_rn((a.z-mu)*rstd*g.z + e.z, (a.w-mu)*rstd*g.w + e.w);
    }
}

// ---------------- xa2 from xn2h -> g_cat[:, 0:1536] --------------------------
__global__ __launch_bounds__(256) void xa2_kernel(const float* __restrict__ adj)
{
    __shared__ float sadjT[Kn * Jn * 18];
    int tid = threadIdx.x;
    for (int i = tid; i < Kn*Jn*Jn; i += 256) { int k = i/289, r = i%289, v = r/17, w = r%17; sadjT[(k*17+w)*18 + v] = adj[i]; }
    for (int i = tid; i < Kn*Jn; i += 256) sadjT[i*18 + 17] = 0.f;
    __syncthreads();

    int gi = blockIdx.x * 256 + tid;
    int b = gi >> 9, c = gi & 511;
    float xv[18];
    #pragma unroll
    for (int v = 0; v < Jn; v++) xv[v] = __half2float(g_xn2h[(size_t)b*(Jn*Cn) + v*Cn + c]);
    xv[17] = 0.f;
    #pragma unroll
    for (int k = 0; k < Kn; k++) {
        #pragma unroll
        for (int w = 0; w < Jn; w++) {
            const float2* ar = (const float2*)&sadjT[(k*17+w)*18];
            float s = 0.f;
            #pragma unroll
            for (int p = 0; p < 9; p++) { float2 a = ar[p]; s += a.x*xv[2*p] + a.y*xv[2*p+1]; }
            g_cat[(size_t)(b*17 + w)*KCAT + k*Cn + c] = __float2half_rn(s);
        }
    }
}

// ---------------- fp16 tensor-core GEMM, 128x128x32, 6-stage cp.async --------
// EPI 0: x2 += acc + b1m[(r%17)*512+c]                  (float out, stride 512)
// EPI 1: g_cat[r][1536+c] = gelu_h2(acc + biasv[c])     (half out, stride 3584)
// EPI 2: out = aux + acc + b2m[(r%17)*512+c]            (float out, stride 512)
#define NSTAGE 6
#define ABYTES 8192                      // 128 rows x 64 B
#define STAGE_BYTES (2*ABYTES)           // 16384
#define GEMM_SMEM (NSTAGE*STAGE_BYTES)   // 98304

template<int EPI>
__global__ __launch_bounds__(256, 2) void gemm_f16(
    const __half* __restrict__ A, const __half* __restrict__ Bw,
    void* __restrict__ outp, const float* __restrict__ biasv,
    const float* __restrict__ aux, int Kd)
{
    extern __shared__ __align__(128) char smem[];
    uint32_t sbase;
    asm("{ .reg .u64 t; cvta.to.shared.u64 t, %1; cvt.u32.u64 %0, t; }" : "=r"(sbase) : "l"(smem));

    const int tid  = threadIdx.x;
    const int warp = tid >> 5;
    const int lane = tid & 31;
    const int m0 = blockIdx.y * 128;
    const int n0 = blockIdx.x * 128;
    const int KT = Kd >> 5;

    const int lrow = tid >> 1;
    const int gsel = tid & 1;
    const int xw   = (lrow & 6) >> 1;
    const __half* gA = A  + (size_t)(m0 + lrow) * Kd + gsel * 16;
    const __half* gB = Bw + (size_t)(n0 + lrow) * Kd + gsel * 16;
    const uint32_t dA0 = sbase + lrow*64 + (((gsel*2 + 0) ^ xw) << 4);
    const uint32_t dA1 = sbase + lrow*64 + (((gsel*2 + 1) ^ xw) << 4);
    const uint32_t dB0 = dA0 + ABYTES;
    const uint32_t dB1 = dA1 + ABYTES;

    #pragma unroll
    for (int s = 0; s < NSTAGE - 1; s++) {
        const uint32_t so = s * STAGE_BYTES;
        if (s < KT) {
            cpasync16(dA0 + so, gA + s*32);
            cpasync16(dA1 + so, gA + s*32 + 8);
            cpasync16(dB0 + so, gB + s*32);
            cpasync16(dB1 + so, gB + s*32 + 8);
        }
        cp_commit();
    }

    const int wm = warp >> 2, wn = warp & 3;
    const int quad = lane >> 3, qr = lane & 7;
    const int kq = quad >> 1;
    const int arow0 = wm*64 + (quad & 1)*8 + qr;
    const int brow0 = wn*32 + (quad & 1)*8 + qr;
    const int xwa = (arow0 & 6) >> 1;
    const int xwb = (brow0 & 6) >> 1;
    const uint32_t aAddr = sbase + arow0*64;
    const uint32_t bAddr = sbase + ABYTES + brow0*64;

    float acc[4][4][4];
    #pragma unroll
    for (int mi = 0; mi < 4; mi++)
        #pragma unroll
        for (int ni = 0; ni < 4; ni++)
            #pragma unroll
            for (int e = 0; e < 4; e++) acc[mi][ni][e] = 0.f;

    int so_it = 0;
    for (int it = 0; it < KT; it++) {
        cp_wait<NSTAGE - 2>();
        __syncthreads();

        if (it + NSTAGE - 1 < KT) {
            int sn = so_it + NSTAGE - 1;
            if (sn >= NSTAGE) sn -= NSTAGE;
            const uint32_t so = sn * STAGE_BYTES;
            const __half* ga = gA + (it + NSTAGE - 1)*32;
            const __half* gb = gB + (it + NSTAGE - 1)*32;
            cpasync16(dA0 + so, ga);
            cpasync16(dA1 + so, ga + 8);
            cpasync16(dB0 + so, gb);
            cpasync16(dB1 + so, gb + 8);
        }
        cp_commit();

        const uint32_t so = so_it * STAGE_BYTES;
        so_it = (so_it + 1 == NSTAGE) ? 0 : so_it + 1;
        #pragma unroll
        for (int ks = 0; ks < 2; ks++) {
            uint32_t af[4][4], bf[2][4];
            #pragma unroll
            for (int mi = 0; mi < 4; mi++)
                ldsm4(af[mi], aAddr + so + mi*1024 + (((ks*2 + kq) ^ xwa) << 4));
            #pragma unroll
            for (int nb = 0; nb < 2; nb++)
                ldsm4(bf[nb], bAddr + so + nb*1024 + (((ks*2 + kq) ^ xwb) << 4));
            #pragma unroll
            for (int mi = 0; mi < 4; mi++)
                #pragma unroll
                for (int ni = 0; ni < 4; ni++) {
                    uint32_t bb[2] = { bf[ni >> 1][ni & 1], bf[ni >> 1][(ni & 1) + 2] };
                    mma_f16(acc[mi][ni], af[mi], bb);
                }
        }
    }

    const int g = lane >> 2, tg = lane & 3;
    #pragma unroll
    for (int mi = 0; mi < 4; mi++) {
        const int rbm = m0 + wm*64 + mi*16 + g;
        #pragma unroll
        for (int half = 0; half < 2; half++) {
            const int r = rbm + half*8;
            #pragma unroll
            for (int ni = 0; ni < 4; ni++) {
                const int c = n0 + wn*32 + ni*8 + tg*2;
                const float v0 = acc[mi][ni][half*2 + 0];
                const float v1 = acc[mi][ni][half*2 + 1];
                if (EPI == 0) {
                    float* p = (float*)outp + (size_t)r * 512 + c;
                    const float* bb = biasv + (r % 17) * 512 + c;
                    float2 o = *(float2*)p;
                    o.x += v0 + bb[0]; o.y += v1 + bb[1];
                    *(float2*)p = o;
                } else if (EPI == 1) {
                    __half2* p = (__half2*)((__half*)outp + (size_t)r * KCAT + KC + c);
                    const float* bb = biasv + c;
                    *p = gelu_h2(__floats2half2_rn(v0 + bb[0], v1 + bb[1]));
                } else {
                    float* p = (float*)outp + (size_t)r * 512 + c;
                    const float* ax = aux + (size_t)r * 512 + c;
                    const float* bb = biasv + (r % 17) * 512 + c;
                    float2 a = *(const float2*)ax;
                    float2 o;
                    o.x = a.x + v0 + bb[0]; o.y = a.y + v1 + bb[1];
                    *(float2*)p = o;
                }
            }
        }
    }
}

// ---------------- launch ------------------------------------------------------
extern "C" void kernel_launch(void* const* d_in, const int* in_sizes, int n_in,
                              void* d_out, int out_size)
{
    const float* x   = (const float*)d_in[0];
    const float* adj = (const float*)d_in[1];
    const float* g1  = (const float*)d_in[2];
    const float* be1 = (const float*)d_in[3];
    const float* g2  = (const float*)d_in[4];
    const float* be2 = (const float*)d_in[5];
    const float* Wg1 = (const float*)d_in[6];
    const float* bg1 = (const float*)d_in[7];
    const float* Wg2 = (const float*)d_in[8];
    const float* bg2 = (const float*)d_in[9];
    const float* W11 = (const float*)d_in[10];
    const float* b11 = (const float*)d_in[11];
    const float* W12 = (const float*)d_in[12];
    const float* b12 = (const float*)d_in[13];
    const float* W21 = (const float*)d_in[14];
    const float* b21 = (const float*)d_in[15];
    const float* W22 = (const float*)d_in[16];
    const float* b22 = (const float*)d_in[17];
    float* out = (float*)d_out;

    __half *p_xah, *p_xn2h, *p_cat, *p_Wr1h, *p_Wcat, *p_W21h;
    float *p_x2, *p_b1m, *p_b2m;
    cudaGetSymbolAddress((void**)&p_xah,  g_xah);
    cudaGetSymbolAddress((void**)&p_x2,   g_x2);
    cudaGetSymbolAddress((void**)&p_xn2h, g_xn2h);
    cudaGetSymbolAddress((void**)&p_cat,  g_cat);
    cudaGetSymbolAddress((void**)&p_Wr1h, g_Wr1h);
    cudaGetSymbolAddress((void**)&p_Wcat, g_Wcat);
    cudaGetSymbolAddress((void**)&p_W21h, g_W21h);
    cudaGetSymbolAddress((void**)&p_b1m,  g_b1m);
    cudaGetSymbolAddress((void**)&p_b2m,  g_b2m);

    static cudaStream_t s2 = nullptr;
    static cudaEvent_t evFork = nullptr, evJoin = nullptr, evFork2 = nullptr, evJoin2 = nullptr;
    if (s2 == nullptr) {
        cudaStreamCreateWithFlags(&s2, cudaStreamNonBlocking);
        cudaEventCreateWithFlags(&evFork,  cudaEventDisableTiming);
        cudaEventCreateWithFlags(&evJoin,  cudaEventDisableTiming);
        cudaEventCreateWithFlags(&evFork2, cudaEventDisableTiming);
        cudaEventCreateWithFlags(&evJoin2, cudaEventDisableTiming);
        cudaFuncSetAttribute(gemm_f16<0>, cudaFuncAttributeMaxDynamicSharedMemorySize, GEMM_SMEM);
        cudaFuncSetAttribute(gemm_f16<1>, cudaFuncAttributeMaxDynamicSharedMemorySize, GEMM_SMEM);
        cudaFuncSetAttribute(gemm_f16<2>, cudaFuncAttributeMaxDynamicSharedMemorySize, GEMM_SMEM);
        cudaFuncSetAttribute(mlp1_kernel, cudaFuncAttributeMaxDynamicSharedMemorySize, M1_SMEM);
    }

    // fork 1: prep (weights only) on s2, concurrent with stage1 on main stream
    cudaEventRecord(evFork, 0);
    cudaStreamWaitEvent(s2, evFork, 0);
    {
        int total = Cn*KC + Cn*KCAT + CHn*Cn + TOKn*16 + TOKn + 32*TOKn + 2*(Jn*Cn);
        prep_kernel<<<(total + 255)/256, 256, 0, s2>>>(Wg1, Wg2, W21, W22, bg1, bg2, adj, W11, W12, b22);
    }
    cudaEventRecord(evJoin, s2);

    // stage1 on main (overlaps prep)
    stage1_kernel<<<Bsz, 256>>>(x, adj, g1, be1);
    cudaStreamWaitEvent(0, evJoin, 0);

    // mlp1, GCN1, LN2 on main
    mlp1_kernel<<<MR/128, 256, M1_SMEM>>>(x, b11, b12);
    gemm_f16<0><<<dim3(Cn/128, M2/128), 256, GEMM_SMEM>>>(p_xah, p_Wr1h, p_x2, p_b1m, nullptr, KC);
    ln2_kernel<<<M2/8, 256>>>(g2, be2);

    // fork 2: xa2 (memory-bound, writes g_cat[:,0:1536]) on s2,
    //         concurrent with gemm1 (tensor-bound, writes g_cat[:,1536:]) on main
    cudaEventRecord(evFork2, 0);
    cudaStreamWaitEvent(s2, evFork2, 0);
    xa2_kernel<<<(Bsz*Cn)/256, 256, 0, s2>>>(adj);
    cudaEventRecord(evJoin2, s2);

    gemm_f16<1><<<dim3(CHn/128, M2/128), 256, GEMM_SMEM>>>(p_xn2h, p_W21h, p_cat, b21, nullptr, Cn);

    // join: gemm2 needs both g_cat halves
    cudaStreamWaitEvent(0, evJoin2, 0);

    // final fused GCN2+MLP2dn: out = x2 + cat @ Wcat^T + b2m'   (K=3584, N=512)
    gemm_f16<2><<<dim3(Cn/128, M2/128), 256, GEMM_SMEM>>>(p_cat, p_Wcat, out, p_b2m, p_x2, KCAT);
}

// round 17
// speedup vs baseline: 1.0404x; 1.0119x over previous
#include <cuda_runtime.h>
#include <cuda_fp16.h>
#include <math.h>
#include <stdint.h>

// Problem constants
#define Bsz 4096
#define Jn  17
#define Cn  512
#define Kn  3
#define TOKn 256
#define CHn 2048
#define M2  (Bsz*Jn)       // 69632
#define KC  (Kn*Cn)        // 1536
#define KCAT (KC + CHn)    // 3584
#define MR  (Bsz*Cn)       // 2097152 rows of (b,c)
#define EPSF 1e-5f

// ---------------- scratch (device globals; allocation-free rule) -------------
__device__ __half g_xah [M2 * KC];        // xa1, fp16                (214 MB)
__device__ float  g_x2  [Bsz*Jn*Cn];      // stage-1 result, fp32     (143 MB)
__device__ __half g_xn2h[Bsz*Jn*Cn];      // LN2 output, fp16         (71 MB)
__device__ __half g_cat [(size_t)M2 * KCAT]; // [xa2 | h], fp16       (499 MB)
__device__ __half g_xnh [(size_t)MR * 16];   // LN1 xn, k=16          (67 MB)
__device__ __half g_xn16[(size_t)MR];        // LN1 xn element 16     (4 MB)
__device__ __half g_Wr1h[Cn * KC];        // [o][k*512+c]
__device__ __half g_Wcat[Cn * KCAT];      // [o][Wr2 | W22]
__device__ __half g_W21h[CHn * Cn];       // [ch][c]
__device__ __half g_W11h[TOKn * 16];      // [t][j 0..15]
__device__ float  g_w11c16[TOKn];         // W11[t][16]
__device__ __half g_W12h[32 * TOKn];      // [j pad 32][t]
__device__ float  g_b1m [Jn * Cn];
__device__ float  g_b2m [Jn * Cn];        // includes b22

__device__ __forceinline__ uint32_t h2u(__half2 h) { return *(uint32_t*)&h; }

// packed half2 gelu: tanh formulation with HW tanh.approx.f16x2 (1 MUFU / 2 vals)
__device__ __forceinline__ __half2 gelu_h2(__half2 v) {
    const __half2 c0 = __floats2half2_rn(0.7978845608f, 0.7978845608f);
    const __half2 c1 = __floats2half2_rn(0.0356774081f, 0.0356774081f);
    const __half2 hhalf = __floats2half2_rn(0.5f, 0.5f);
    const __half2 hone  = __floats2half2_rn(1.0f, 1.0f);
    __half2 v2 = __hmul2(v, v);
    __half2 inner = __hmul2(v, __hfma2(c1, v2, c0));
    uint32_t t;
    asm("tanh.approx.f16x2 %0, %1;" : "=r"(t) : "r"(h2u(inner)));
    __half2 th = *(__half2*)&t;
    return __hmul2(__hmul2(hhalf, v), __hadd2(hone, th));
}

// ---------------- PTX helpers ------------------------------------------------
__device__ __forceinline__ void mma_f16(float* d, const uint32_t* a, const uint32_t* b) {
    asm volatile(
        "mma.sync.aligned.m16n8k16.row.col.f32.f16.f16.f32 "
        "{%0,%1,%2,%3}, {%4,%5,%6,%7}, {%8,%9}, {%0,%1,%2,%3};"
        : "+f"(d[0]), "+f"(d[1]), "+f"(d[2]), "+f"(d[3])
        : "r"(a[0]), "r"(a[1]), "r"(a[2]), "r"(a[3]), "r"(b[0]), "r"(b[1]));
}
__device__ __forceinline__ void ldsm4(uint32_t* r, uint32_t addr) {
    asm volatile("ldmatrix.sync.aligned.m8n8.x4.shared.b16 {%0,%1,%2,%3}, [%4];"
                 : "=r"(r[0]), "=r"(r[1]), "=r"(r[2]), "=r"(r[3]) : "r"(addr));
}
__device__ __forceinline__ void cpasync16(uint32_t smem, const void* g) {
    asm volatile("cp.async.cg.shared.global [%0], [%1], 16;" :: "r"(smem), "l"(g));
}
__device__ __forceinline__ void cp_commit() {
    asm volatile("cp.async.commit_group;" ::: "memory");
}
template<int N_> __device__ __forceinline__ void cp_wait() {
    asm volatile("cp.async.wait_group %0;" :: "n"(N_) : "memory");
}

// ---------------- prep: weight layouts (fp16) + gcn bias ---------------------
__global__ void prep_kernel(const float* __restrict__ Wg1, const float* __restrict__ Wg2,
                            const float* __restrict__ W21, const float* __restrict__ W22,
                            const float* __restrict__ bg1, const float* __restrict__ bg2,
                            const float* __restrict__ adj,
                            const float* __restrict__ W11, const float* __restrict__ W12,
                            const float* __restrict__ b22)
{
    int i = blockIdx.x * 256 + threadIdx.x;
    const int S_Wr1 = Cn * KC;
    const int S_Wcat = Cn * KCAT;
    const int S_W21 = CHn * Cn;
    if (i < S_Wr1) {
        int o = i / KC, rem = i % KC;
        int k = rem >> 9, c = rem & 511;
        g_Wr1h[i] = __float2half_rn(Wg1[k * (Cn*Cn) + o * Cn + c]);
        return;
    }
    i -= S_Wr1;
    if (i < S_Wcat) {
        int o = i / KCAT, kk = i % KCAT;
        float v;
        if (kk < KC) {
            int k = kk >> 9, c = kk & 511;
            v = Wg2[k * (Cn*Cn) + o * Cn + c];
        } else {
            v = W22[o * CHn + (kk - KC)];
        }
        g_Wcat[i] = __float2half_rn(v);
        return;
    }
    i -= S_Wcat;
    if (i < S_W21) { g_W21h[i] = __float2half_rn(W21[i]); return; }
    i -= S_W21;
    if (i < TOKn * 16) {
        int t = i >> 4, j = i & 15;
        g_W11h[i] = __float2half_rn(W11[t * Jn + j]);
        return;
    }
    i -= TOKn * 16;
    if (i < TOKn) { g_w11c16[i] = W11[i * Jn + 16]; return; }
    i -= TOKn;
    if (i < 32 * TOKn) {
        int n = i >> 8, t = i & 255;
        g_W12h[i] = (n < Jn) ? __float2half_rn(W12[n * TOKn + t]) : __half(0.f);
        return;
    }
    i -= 32 * TOKn;
    if (i < Jn * Cn) {
        int w = i >> 9, o = i & 511;
        float s = 0.f;
        #pragma unroll
        for (int k = 0; k < Kn; k++) {
            float cs = 0.f;
            #pragma unroll
            for (int v = 0; v < Jn; v++) cs += adj[k*289 + v*17 + w];
            s += bg1[k * Cn + o] * cs;
        }
        g_b1m[i] = s;
        return;
    }
    i -= Jn * Cn;
    if (i < Jn * Cn) {
        int w = i >> 9, o = i & 511;
        float s = b22[o];
        #pragma unroll
        for (int k = 0; k < Kn; k++) {
            float cs = 0.f;
            #pragma unroll
            for (int v = 0; v < Jn; v++) cs += adj[k*289 + v*17 + w];
            s += bg2[k * Cn + o] * cs;
        }
        g_b2m[i] = s;
        return;
    }
}

// ---------------- stage 1: LN(J) -> xa1(fp16) + xnh(fp16, k16) + xn16 --------
// thread t owns ADJACENT columns 2t, 2t+1 -> all fp16 stores are __half2
__global__ __launch_bounds__(256) void stage1_kernel(
    const float* __restrict__ x, const float* __restrict__ adj,
    const float* __restrict__ g1, const float* __restrict__ be1)
{
    __shared__ float sadjT[Kn * Jn * 18];
    __shared__ float sg1[Jn], sbe1[Jn];

    const int tid = threadIdx.x;
    const int b = blockIdx.x;

    for (int i = tid; i < Kn*Jn*Jn; i += 256) { int k = i/289, r = i%289, v = r/17, w = r%17; sadjT[(k*17+w)*18 + v] = adj[i]; }
    for (int i = tid; i < Kn*Jn; i += 256) sadjT[i*18 + 17] = 0.f;
    if (tid < Jn) { sg1[tid] = g1[tid]; sbe1[tid] = be1[tid]; }
    __syncthreads();

    const int c0 = tid * 2;
    const float2* xb2 = (const float2*)(x + (size_t)b * (Jn*Cn));

    float xr0[Jn], xr1[Jn];
    #pragma unroll
    for (int j = 0; j < Jn; j++) { float2 v = xb2[j*256 + tid]; xr0[j] = v.x; xr1[j] = v.y; }

    float mu0 = 0.f, mu1 = 0.f;
    #pragma unroll
    for (int j = 0; j < Jn; j++) { mu0 += xr0[j]; mu1 += xr1[j]; }
    mu0 *= (1.0f/17.0f); mu1 *= (1.0f/17.0f);
    float v0 = 0.f, v1 = 0.f;
    #pragma unroll
    for (int j = 0; j < Jn; j++) { float d0 = xr0[j]-mu0, d1 = xr1[j]-mu1; v0 += d0*d0; v1 += d1*d1; }
    float rs0 = rsqrtf(v0*(1.0f/17.0f) + EPSF);
    float rs1 = rsqrtf(v1*(1.0f/17.0f) + EPSF);

    float xn0[18], xn1[18];
    #pragma unroll
    for (int j = 0; j < Jn; j++) {
        xn0[j] = (xr0[j]-mu0)*rs0*sg1[j] + sbe1[j];
        xn1[j] = (xr1[j]-mu1)*rs1*sg1[j] + sbe1[j];
    }
    xn0[17] = 0.f; xn1[17] = 0.f;

    // xa1 (fp16, __half2 stores)
    #pragma unroll
    for (int k = 0; k < Kn; k++) {
        #pragma unroll
        for (int w = 0; w < Jn; w++) {
            const float2* ar = (const float2*)&sadjT[(k*17+w)*18];
            float s0 = 0.f, s1 = 0.f;
            #pragma unroll
            for (int p = 0; p < 9; p++) {
                float2 a = ar[p];
                s0 += a.x*xn0[2*p] + a.y*xn0[2*p+1];
                s1 += a.x*xn1[2*p] + a.y*xn1[2*p+1];
            }
            int idx = (b*17 + w)*KC + k*Cn + c0;
            *(__half2*)&g_xah[idx] = __floats2half2_rn(s0, s1);
        }
    }

    // xnh: rows (b*512+c0) and (b*512+c0+1) are contiguous (16 halves each)
    // -> single 64B contiguous write per thread
    {
        __half2 hx[16];
        #pragma unroll
        for (int p = 0; p < 8; p++) hx[p]     = __floats2half2_rn(xn0[2*p], xn0[2*p+1]);
        #pragma unroll
        for (int p = 0; p < 8; p++) hx[8 + p] = __floats2half2_rn(xn1[2*p], xn1[2*p+1]);
        uint4* d0 = (uint4*)(g_xnh + ((size_t)b*512 + c0) * 16);
        const uint4* s = (const uint4*)hx;
        d0[0] = s[0]; d0[1] = s[1]; d0[2] = s[2]; d0[3] = s[3];
        *(__half2*)&g_xn16[(size_t)b*512 + c0] = __floats2half2_rn(xn0[16], xn1[16]);
    }
}

// ---------------- fused MLP1 on tensor cores (k=16 + rank-1) -----------------
#define M1_XN   0            // [128][48B]   6144
#define M1_W11  6144         // [256][48B]   12288
#define M1_W12  18432        // [32][512B]   16384 (swizzled)
#define M1_X16  34816        // 128 floats
#define M1_WC16 35328        // 256 floats
#define M1_B11  36352        // 256 floats
#define M1_B12  37376        // 17 floats
#define M1_SMEM 37504

__global__ __launch_bounds__(256, 2) void mlp1_kernel(
    const float* __restrict__ x,
    const float* __restrict__ b11, const float* __restrict__ b12)
{
    extern __shared__ __align__(128) char sm[];
    uint32_t sbase;
    asm("{ .reg .u64 t; cvta.to.shared.u64 t, %1; cvt.u32.u64 %0, t; }" : "=r"(sbase) : "l"(sm));
    float* sx16  = (float*)(sm + M1_X16);
    float* swc16 = (float*)(sm + M1_WC16);
    float* sb11  = (float*)(sm + M1_B11);
    float* sb12  = (float*)(sm + M1_B12);

    const int tid = threadIdx.x, warp = tid >> 5, lane = tid & 31;
    const int rb = blockIdx.x * 128;

    {   // xnh tile: 128 rows x 32B, pitch 48
        const int r = tid >> 1, g = tid & 1;
        cpasync16(sbase + M1_XN + r*48 + g*16, g_xnh + ((size_t)(rb + r))*16 + g*8);
    }
    #pragma unroll
    for (int i = 0; i < 2; i++) {
        int ci = tid + 256*i;
        int row = ci >> 1, g = ci & 1;
        cpasync16(sbase + M1_W11 + row*48 + g*16, g_W11h + row*16 + g*8);
    }
    #pragma unroll
    for (int i = 0; i < 4; i++) {
        int ci = tid + 256*i;
        int row = ci >> 5, g = ci & 31;
        int gp = (g & ~7) | ((g ^ row) & 7);
        cpasync16(sbase + M1_W12 + row*512 + gp*16, g_W12h + row*256 + g*8);
    }
    cp_commit();
    if (tid < 128) sx16[tid] = __half2float(g_xn16[rb + tid]);
    swc16[tid] = g_w11c16[tid];
    sb11[tid] = b11[tid];
    if (tid < Jn) sb12[tid] = b12[tid];
    cp_wait<0>();
    __syncthreads();

    const int quad = lane >> 3, qr = lane & 7;
    const int kq = quad >> 1, qh = quad & 1;
    const int g = lane >> 2, tg = lane & 3;

    uint32_t af[4];
    ldsm4(af, sbase + M1_XN + (warp*16 + qh*8 + qr)*48 + (kq << 4));
    const float xnr0 = sx16[warp*16 + g];
    const float xnr1 = sx16[warp*16 + g + 8];

    float oacc[3][4];
    #pragma unroll
    for (int n = 0; n < 3; n++)
        #pragma unroll
        for (int e = 0; e < 4; e++) oacc[n][e] = 0.f;

    #pragma unroll
    for (int q = 0; q < 4; q++) {
        float hacc[8][4];
        #pragma unroll
        for (int n = 0; n < 8; n++)
            #pragma unroll
            for (int e = 0; e < 4; e++) hacc[n][e] = 0.f;

        #pragma unroll
        for (int nb = 0; nb < 4; nb++) {
            uint32_t bf[4];
            ldsm4(bf, sbase + M1_W11 + (q*64 + nb*16 + qh*8 + qr)*48 + (kq << 4));
            #pragma unroll
            for (int ni = 0; ni < 2; ni++) {
                uint32_t bb[2] = { bf[ni], bf[ni + 2] };
                mma_f16(hacc[nb*2 + ni], af, bb);
            }
        }

        uint32_t h2[8][2];
        #pragma unroll
        for (int nt = 0; nt < 8; nt++) {
            int t0 = q*64 + nt*8 + tg*2;
            float w0 = swc16[t0], w1 = swc16[t0 + 1];
            float b0 = sb11[t0],  b1 = sb11[t0 + 1];
            __half2 p0 = __floats2half2_rn(hacc[nt][0] + xnr0*w0 + b0,
                                           hacc[nt][1] + xnr0*w1 + b1);
            __half2 p1 = __floats2half2_rn(hacc[nt][2] + xnr1*w0 + b0,
                                           hacc[nt][3] + xnr1*w1 + b1);
            h2[nt][0] = h2u(gelu_h2(p0));
            h2[nt][1] = h2u(gelu_h2(p1));
        }

        #pragma unroll
        for (int ksl = 0; ksl < 4; ksl++) {
            uint32_t a2[4] = { h2[2*ksl][0], h2[2*ksl][1], h2[2*ksl+1][0], h2[2*ksl+1][1] };
            int kgrp = (q*4 + ksl)*2 + kq;
            #pragma unroll
            for (int nb2 = 0; nb2 < 2; nb2++) {
                const int brow = nb2*16 + qh*8 + qr;
                int gp = (kgrp & ~7) | ((kgrp ^ brow) & 7);
                uint32_t bf[4];
                ldsm4(bf, sbase + M1_W12 + brow*512 + (gp << 4));
                #pragma unroll
                for (int ni = 0; ni < 2; ni++) {
                    int nt2 = nb2*2 + ni;
                    if (nt2 < 3) {
                        uint32_t bb[2] = { bf[ni], bf[ni + 2] };
                        mma_f16(oacc[nt2], a2, bb);
                    }
                }
            }
        }
    }

    #pragma unroll
    for (int nt2 = 0; nt2 < 3; nt2++) {
        #pragma unroll
        for (int e = 0; e < 4; e++) {
            int j = nt2*8 + tg*2 + (e & 1);
            if (j < Jn) {
                int rowg = rb + warp*16 + g + ((e >> 1) * 8);
                int b = rowg >> 9, c = rowg & 511;
                size_t idx = ((size_t)b*17 + j)*512 + c;
                g_x2[idx] = x[idx] + oacc[nt2][e] + sb12[j];
            }
        }
    }
}

// ---------------- LN over C=512 (one warp per row), fp16 out -----------------
__global__ __launch_bounds__(256) void ln2_kernel(const float* __restrict__ g2,
                                                  const float* __restrict__ be2)
{
    int row = blockIdx.x * 8 + (threadIdx.x >> 5);
    int lane = threadIdx.x & 31;
    const float4* xr = (const float4*)(g_x2 + (size_t)row * Cn);
    float4 a0 = xr[lane], a1 = xr[lane+32], a2 = xr[lane+64], a3 = xr[lane+96];
    float s = a0.x+a0.y+a0.z+a0.w + a1.x+a1.y+a1.z+a1.w
            + a2.x+a2.y+a2.z+a2.w + a3.x+a3.y+a3.z+a3.w;
    #pragma unroll
    for (int off = 16; off; off >>= 1) s += __shfl_xor_sync(0xffffffffu, s, off);
    float mu = s * (1.0f/512.0f);
    float q = 0.f;
    {
        float d;
        d=a0.x-mu; q+=d*d; d=a0.y-mu; q+=d*d; d=a0.z-mu; q+=d*d; d=a0.w-mu; q+=d*d;
        d=a1.x-mu; q+=d*d; d=a1.y-mu; q+=d*d; d=a1.z-mu; q+=d*d; d=a1.w-mu; q+=d*d;
        d=a2.x-mu; q+=d*d; d=a2.y-mu; q+=d*d; d=a2.z-mu; q+=d*d; d=a2.w-mu; q+=d*d;
        d=a3.x-mu; q+=d*d; d=a3.y-mu; q+=d*d; d=a3.z-mu; q+=d*d; d=a3.w-mu; q+=d*d;
    }
    #pragma unroll
    for (int off = 16; off; off >>= 1) q += __shfl_xor_sync(0xffffffffu, q, off);
    float rstd = rsqrtf(q * (1.0f/512.0f) + EPSF);

    const float4* gg = (const float4*)g2;
    const float4* bb = (const float4*)be2;
    __half2* oh = (__half2*)(g_xn2h + (size_t)row * Cn);
    #pragma unroll
    for (int i = 0; i < 4; i++) {
        float4 a = (i==0)?a0:(i==1)?a1:(i==2)?a2:a3;
        float4 g = gg[lane + i*32], e = bb[lane + i*32];
        int p = (lane + i*32) * 2;
        oh[p]   = __floats2half2_rn((a.x-mu)*rstd*g.x + e.x, (a.y-mu)*rstd*g.y + e.y);
        oh[p+1] = __floats2half2_rn((a.z-mu)*rstd*g.z + e.z, (a.w-mu)*rstd*g.w + e.w);
    }
}

// ---------------- xa2 from xn2h -> g_cat[:, 0:1536] --------------------------
// one block per b; thread t owns adjacent columns 2t, 2t+1 (__half2 ld/st)
__global__ __launch_bounds__(256) void xa2_kernel(const float* __restrict__ adj)
{
    __shared__ float sadjT[Kn * Jn * 18];
    int tid = threadIdx.x;
    for (int i = tid; i < Kn*Jn*Jn; i += 256) { int k = i/289, r = i%289, v = r/17, w = r%17; sadjT[(k*17+w)*18 + v] = adj[i]; }
    for (int i = tid; i < Kn*Jn; i += 256) sadjT[i*18 + 17] = 0.f;
    __syncthreads();

    const int b = blockIdx.x;
    const int c0 = tid * 2;
    float xv0[18], xv1[18];
    #pragma unroll
    for (int v = 0; v < Jn; v++) {
        __half2 h = *(const __half2*)&g_xn2h[(size_t)b*(Jn*Cn) + v*Cn + c0];
        float2 f = __half22float2(h);
        xv0[v] = f.x; xv1[v] = f.y;
    }
    xv0[17] = 0.f; xv1[17] = 0.f;
    #pragma unroll
    for (int k = 0; k < Kn; k++) {
        #pragma unroll
        for (int w = 0; w < Jn; w++) {
            const float2* ar = (const float2*)&sadjT[(k*17+w)*18];
            float s0 = 0.f, s1 = 0.f;
            #pragma unroll
            for (int p = 0; p < 9; p++) {
                float2 a = ar[p];
                s0 += a.x*xv0[2*p] + a.y*xv0[2*p+1];
                s1 += a.x*xv1[2*p] + a.y*xv1[2*p+1];
            }
            *(__half2*)&g_cat[(size_t)(b*17 + w)*KCAT + k*Cn + c0] = __floats2half2_rn(s0, s1);
        }
    }
}

// ---------------- fp16 tensor-core GEMM, 128x128x32, 6-stage cp.async --------
// EPI 0: x2 += acc + b1m[(r%17)*512+c]                  (float out, stride 512)
// EPI 1: g_cat[r][1536+c] = gelu_h2(acc + biasv[c])     (half out, stride 3584)
// EPI 2: out = aux + acc + b2m[(r%17)*512+c]            (float out, stride 512)
#define NSTAGE 6
#define ABYTES 8192                      // 128 rows x 64 B
#define STAGE_BYTES (2*ABYTES)           // 16384
#define GEMM_SMEM (NSTAGE*STAGE_BYTES)   // 98304

template<int EPI>
__global__ __launch_bounds__(256, 2) void gemm_f16(
    const __half* __restrict__ A, const __half* __restrict__ Bw,
    void* __restrict__ outp, const float* __restrict__ biasv,
    const float* __restrict__ aux, int Kd)
{
    extern __shared__ __align__(128) char smem[];
    uint32_t sbase;
    asm("{ .reg .u64 t; cvta.to.shared.u64 t, %1; cvt.u32.u64 %0, t; }" : "=r"(sbase) : "l"(smem));

    const int tid  = threadIdx.x;
    const int warp = tid >> 5;
    const int lane = tid & 31;
    const int m0 = blockIdx.y * 128;
    const int n0 = blockIdx.x * 128;
    const int KT = Kd >> 5;

    const int lrow = tid >> 1;
    const int gsel = tid & 1;
    const int xw   = (lrow & 6) >> 1;
    const __half* gA = A  + (size_t)(m0 + lrow) * Kd + gsel * 16;
    const __half* gB = Bw + (size_t)(n0 + lrow) * Kd + gsel * 16;
    const uint32_t dA0 = sbase + lrow*64 + (((gsel*2 + 0) ^ xw) << 4);
    const uint32_t dA1 = sbase + lrow*64 + (((gsel*2 + 1) ^ xw) << 4);
    const uint32_t dB0 = dA0 + ABYTES;
    const uint32_t dB1 = dA1 + ABYTES;

    #pragma unroll
    for (int s = 0; s < NSTAGE - 1; s++) {
        const uint32_t so = s * STAGE_BYTES;
        if (s < KT) {
            cpasync16(dA0 + so, gA + s*32);
            cpasync16(dA1 + so, gA + s*32 + 8);
            cpasync16(dB0 + so, gB + s*32);
            cpasync16(dB1 + so, gB + s*32 + 8);
        }
        cp_commit();
    }

    const int wm = warp >> 2, wn = warp & 3;
    const int quad = lane >> 3, qr = lane & 7;
    const int kq = quad >> 1;
    const int arow0 = wm*64 + (quad & 1)*8 + qr;
    const int brow0 = wn*32 + (quad & 1)*8 + qr;
    const int xwa = (arow0 & 6) >> 1;
    const int xwb = (brow0 & 6) >> 1;
    const uint32_t aAddr = sbase + arow0*64;
    const uint32_t bAddr = sbase + ABYTES + brow0*64;

    float acc[4][4][4];
    #pragma unroll
    for (int mi = 0; mi < 4; mi++)
        #pragma unroll
        for (int ni = 0; ni < 4; ni++)
            #pragma unroll
            for (int e = 0; e < 4; e++) acc[mi][ni][e] = 0.f;

    int so_it = 0;
    for (int it = 0; it < KT; it++) {
        cp_wait<NSTAGE - 2>();
        __syncthreads();

        if (it + NSTAGE - 1 < KT) {
            int sn = so_it + NSTAGE - 1;
            if (sn >= NSTAGE) sn -= NSTAGE;
            const uint32_t so = sn * STAGE_BYTES;
            const __half* ga = gA + (it + NSTAGE - 1)*32;
            const __half* gb = gB + (it + NSTAGE - 1)*32;
            cpasync16(dA0 + so, ga);
            cpasync16(dA1 + so, ga + 8);
            cpasync16(dB0 + so, gb);
            cpasync16(dB1 + so, gb + 8);
        }
        cp_commit();

        const uint32_t so = so_it * STAGE_BYTES;
        so_it = (so_it + 1 == NSTAGE) ? 0 : so_it + 1;
        #pragma unroll
        for (int ks = 0; ks < 2; ks++) {
            uint32_t af[4][4], bf[2][4];
            #pragma unroll
            for (int mi = 0; mi < 4; mi++)
                ldsm4(af[mi], aAddr + so + mi*1024 + (((ks*2 + kq) ^ xwa) << 4));
            #pragma unroll
            for (int nb = 0; nb < 2; nb++)
                ldsm4(bf[nb], bAddr + so + nb*1024 + (((ks*2 + kq) ^ xwb) << 4));
            #pragma unroll
            for (int mi = 0; mi < 4; mi++)
                #pragma unroll
                for (int ni = 0; ni < 4; ni++) {
                    uint32_t bb[2] = { bf[ni >> 1][ni & 1], bf[ni >> 1][(ni & 1) + 2] };
                    mma_f16(acc[mi][ni], af[mi], bb);
                }
        }
    }

    const int g = lane >> 2, tg = lane & 3;
    #pragma unroll
    for (int mi = 0; mi < 4; mi++) {
        const int rbm = m0 + wm*64 + mi*16 + g;
        #pragma unroll
        for (int half = 0; half < 2; half++) {
            const int r = rbm + half*8;
            #pragma unroll
            for (int ni = 0; ni < 4; ni++) {
                const int c = n0 + wn*32 + ni*8 + tg*2;
                const float v0 = acc[mi][ni][half*2 + 0];
                const float v1 = acc[mi][ni][half*2 + 1];
                if (EPI == 0) {
                    float* p = (float*)outp + (size_t)r * 512 + c;
                    const float* bb = biasv + (r % 17) * 512 + c;
                    float2 o = *(float2*)p;
                    o.x += v0 + bb[0]; o.y += v1 + bb[1];
                    *(float2*)p = o;
                } else if (EPI == 1) {
                    __half2* p = (__half2*)((__half*)outp + (size_t)r * KCAT + KC + c);
                    const float* bb = biasv + c;
                    *p = gelu_h2(__floats2half2_rn(v0 + bb[0], v1 + bb[1]));
                } else {
                    float* p = (float*)outp + (size_t)r * 512 + c;
                    const float* ax = aux + (size_t)r * 512 + c;
                    const float* bb = biasv + (r % 17) * 512 + c;
                    float2 a = *(const float2*)ax;
                    float2 o;
                    o.x = a.x + v0 + bb[0]; o.y = a.y + v1 + bb[1];
                    *(float2*)p = o;
                }
            }
        }
    }
}

// ---------------- launch ------------------------------------------------------
extern "C" void kernel_launch(void* const* d_in, const int* in_sizes, int n_in,
                              void* d_out, int out_size)
{
    const float* x   = (const float*)d_in[0];
    const float* adj = (const float*)d_in[1];
    const float* g1  = (const float*)d_in[2];
    const float* be1 = (const float*)d_in[3];
    const float* g2  = (const float*)d_in[4];
    const float* be2 = (const float*)d_in[5];
    const float* Wg1 = (const float*)d_in[6];
    const float* bg1 = (const float*)d_in[7];
    const float* Wg2 = (const float*)d_in[8];
    const float* bg2 = (const float*)d_in[9];
    const float* W11 = (const float*)d_in[10];
    const float* b11 = (const float*)d_in[11];
    const float* W12 = (const float*)d_in[12];
    const float* b12 = (const float*)d_in[13];
    const float* W21 = (const float*)d_in[14];
    const float* b21 = (const float*)d_in[15];
    const float* W22 = (const float*)d_in[16];
    const float* b22 = (const float*)d_in[17];
    float* out = (float*)d_out;

    __half *p_xah, *p_xn2h, *p_cat, *p_Wr1h, *p_Wcat, *p_W21h;
    float *p_x2, *p_b1m, *p_b2m;
    cudaGetSymbolAddress((void**)&p_xah,  g_xah);
    cudaGetSymbolAddress((void**)&p_x2,   g_x2);
    cudaGetSymbolAddress((void**)&p_xn2h, g_xn2h);
    cudaGetSymbolAddress((void**)&p_cat,  g_cat);
    cudaGetSymbolAddress((void**)&p_Wr1h, g_Wr1h);
    cudaGetSymbolAddress((void**)&p_Wcat, g_Wcat);
    cudaGetSymbolAddress((void**)&p_W21h, g_W21h);
    cudaGetSymbolAddress((void**)&p_b1m,  g_b1m);
    cudaGetSymbolAddress((void**)&p_b2m,  g_b2m);

    static cudaStream_t s2 = nullptr;
    static cudaEvent_t evFork = nullptr, evJoin = nullptr, evFork2 = nullptr, evJoin2 = nullptr;
    if (s2 == nullptr) {
        cudaStreamCreateWithFlags(&s2, cudaStreamNonBlocking);
        cudaEventCreateWithFlags(&evFork,  cudaEventDisableTiming);
        cudaEventCreateWithFlags(&evJoin,  cudaEventDisableTiming);
        cudaEventCreateWithFlags(&evFork2, cudaEventDisableTiming);
        cudaEventCreateWithFlags(&evJoin2, cudaEventDisableTiming);
        cudaFuncSetAttribute(gemm_f16<0>, cudaFuncAttributeMaxDynamicSharedMemorySize, GEMM_SMEM);
        cudaFuncSetAttribute(gemm_f16<1>, cudaFuncAttributeMaxDynamicSharedMemorySize, GEMM_SMEM);
        cudaFuncSetAttribute(gemm_f16<2>, cudaFuncAttributeMaxDynamicSharedMemorySize, GEMM_SMEM);
        cudaFuncSetAttribute(mlp1_kernel, cudaFuncAttributeMaxDynamicSharedMemorySize, M1_SMEM);
    }

    // fork 1: prep (weights only) on s2, concurrent with stage1 on main stream
    cudaEventRecord(evFork, 0);
    cudaStreamWaitEvent(s2, evFork, 0);
    {
        int total = Cn*KC + Cn*KCAT + CHn*Cn + TOKn*16 + TOKn + 32*TOKn + 2*(Jn*Cn);
        prep_kernel<<<(total + 255)/256, 256, 0, s2>>>(Wg1, Wg2, W21, W22, bg1, bg2, adj, W11, W12, b22);
    }
    cudaEventRecord(evJoin, s2);

    // stage1 on main (overlaps prep)
    stage1_kernel<<<Bsz, 256>>>(x, adj, g1, be1);
    cudaStreamWaitEvent(0, evJoin, 0);

    // mlp1, GCN1, LN2 on main
    mlp1_kernel<<<MR/128, 256, M1_SMEM>>>(x, b11, b12);
    gemm_f16<0><<<dim3(Cn/128, M2/128), 256, GEMM_SMEM>>>(p_xah, p_Wr1h, p_x2, p_b1m, nullptr, KC);
    ln2_kernel<<<M2/8, 256>>>(g2, be2);

    // fork 2: xa2 (memory-bound, writes g_cat[:,0:1536]) on s2,
    //         concurrent with gemm1 (tensor-bound, writes g_cat[:,1536:]) on main
    cudaEventRecord(evFork2, 0);
    cudaStreamWaitEvent(s2, evFork2, 0);
    xa2_kernel<<<Bsz, 256, 0, s2>>>(adj);
    cudaEventRecord(evJoin2, s2);

    gemm_f16<1><<<dim3(CHn/128, M2/128), 256, GEMM_SMEM>>>(p_xn2h, p_W21h, p_cat, b21, nullptr, Cn);

    // join: gemm2 needs both g_cat halves
    cudaStreamWaitEvent(0, evJoin2, 0);

    // final fused GCN2+MLP2dn: out = x2 + cat @ Wcat^T + b2m'   (K=3584, N=512)
    gemm_f16<2><<<dim3(Cn/128, M2/128), 256, GEMM_SMEM>>>(p_cat, p_Wcat, out, p_b2m, p_x2, KCAT);
}